// round 7
// baseline (speedup 1.0000x reference)
#include <cuda_runtime.h>
#include <cstdint>

#define CIN   6
#define COUT  16
#define FS    5
#define HIN   512
#define WIN   512
#define HOUT  508
#define WOUT  508
#define BATCHN 32

// ---- dense weights (fp32), built per launch ----
__device__ float g_Wd[FS * FS * CIN * COUT];

__global__ void build_weights(const float* __restrict__ w3,
                              const float* __restrict__ w4,
                              const float* __restrict__ w44,
                              const float* __restrict__ w6) {
    int idx = blockIdx.x * blockDim.x + threadIdx.x;
    if (idx >= FS * FS * CIN * COUT) return;
    int co = idx % COUT;
    int ci = (idx / COUT) % CIN;
    int kk = idx / (COUT * CIN);
    float v = 0.f;
    if (co < 6) {
        int i = co;
        #pragma unroll
        for (int m = 0; m < 3; ++m)
            if (ci == (i + m) % 6) v = w3[(kk * 3 + m) * 6 + i];
    } else if (co < 12) {
        int k = co - 6;
        #pragma unroll
        for (int m = 0; m < 4; ++m)
            if (ci == (k + m) % 6) v = w4[(kk * 4 + m) * 6 + k];
    } else if (co < 15) {
        int k = co - 12;
        const int off[4] = {0, 1, 3, 4};
        #pragma unroll
        for (int m = 0; m < 4; ++m)
            if (ci == (k + off[m]) % 6) v = w44[(kk * 4 + m) * 3 + k];
    } else {
        v = w6[kk * 6 + ci];
    }
    g_Wd[idx] = v;
}

// ============== mma.sync tf32 conv, operand-swapped ==============
// Per mma: D[16 px][8 co]. A = input (m16 px x k8), B = weights (k8 x n8 co).
// K slots = ci permuted [0,4,1,5,2,6,3,7]; slots 5,7 zero. 16 couts = 2 MMAs.
// CTA: 8 warps; tile 8 rows x 64 cols; warp w owns row w = 4 m-tiles of 16 px.

#define TW    64
#define RT    8
#define AROWS (RT + 4)    // 12
#define ACOLS (TW + 4)    // 68

__device__ __forceinline__ uint32_t cvt_tf32(float f) {
    uint32_t u;
    asm("cvt.rna.tf32.f32 %0, %1;" : "=r"(u) : "f"(f));
    return u;
}

__device__ __forceinline__ void mma_tf32(float d[4],
                                         uint32_t a0, uint32_t a1,
                                         uint32_t a2, uint32_t a3,
                                         uint32_t b0, uint32_t b1) {
    asm volatile(
        "mma.sync.aligned.m16n8k8.row.col.f32.tf32.tf32.f32 "
        "{%0,%1,%2,%3}, {%4,%5,%6,%7}, {%8,%9}, {%0,%1,%2,%3};"
        : "+f"(d[0]), "+f"(d[1]), "+f"(d[2]), "+f"(d[3])
        : "r"(a0), "r"(a1), "r"(a2), "r"(a3), "r"(b0), "r"(b1));
}

__global__ __launch_bounds__(256, 3) void conv_mma_kernel(
    const float* __restrict__ in,
    const float* __restrict__ bias,
    float* __restrict__ out) {

    __shared__ uint32_t s_in[AROWS][ACOLS][8];   // 26112 B
    __shared__ uint32_t s_w[25][COUT][8];        // 12800 B
    __shared__ float s_bias[COUT];

    const int tid = threadIdx.x;
    const int b  = blockIdx.z;
    const int y0 = blockIdx.y * RT;
    const int x0 = blockIdx.x * TW;

    // ---- stage weights (permuted K slots; pad slots 5,7 zero) ----
    for (int i = tid; i < 25 * COUT; i += 256) {
        int tap = i / COUT, co = i % COUT;
        s_w[tap][co][5] = 0;
        s_w[tap][co][7] = 0;
    }
    for (int i = tid; i < 25 * COUT * CIN; i += 256) {
        int tap = i / (COUT * CIN);
        int r   = i % (COUT * CIN);
        int co  = r / CIN;
        int ci  = r % CIN;
        int slot = 2 * (ci & 3) + (ci >> 2);
        s_w[tap][co][slot] = cvt_tf32(g_Wd[(tap * CIN + ci) * COUT + co]);
    }
    if (tid < COUT) s_bias[tid] = bias[tid];

    // ---- stage input tile ----
    for (int i = tid; i < AROWS * ACOLS; i += 256) {
        int r = i / ACOLS, c = i % ACOLS;
        s_in[r][c][5] = 0;
        s_in[r][c][7] = 0;
    }
    const float* inb = in + (long long)b * (HIN * WIN * CIN);
    for (int i = tid; i < AROWS * ACOLS * CIN; i += 256) {
        int r   = i / (ACOLS * CIN);
        int rem = i - r * (ACOLS * CIN);
        int c   = rem / CIN;
        int ci  = rem - c * CIN;
        int gy = y0 + r, gx = x0 + c;
        float v = 0.f;
        if (gy < HIN && gx < WIN)
            v = inb[(gy * WIN + gx) * CIN + ci];
        int slot = 2 * (ci & 3) + (ci >> 2);
        s_in[r][c][slot] = cvt_tf32(v);
    }
    __syncthreads();

    const int w    = tid >> 5;    // warp = output row in tile
    const int lane = tid & 31;
    const int g    = lane >> 2;   // group: A rows (px g, g+8); D rows; B col (co g)
    const int tq   = lane & 3;    // thread-in-group: K slots tq, tq+4

    // d[mt][h][4]: m-tile mt (16 px), co-half h
    float d[4][2][4];
    #pragma unroll
    for (int mt = 0; mt < 4; ++mt)
        #pragma unroll
        for (int h = 0; h < 2; ++h)
            #pragma unroll
            for (int q = 0; q < 4; ++q) d[mt][h][q] = 0.f;

    // Base pointers: all inner LDS offsets become immediates.
    const uint32_t* wbase = &s_w[0][g][2 * tq];        // + tap*128 u32, +8*8 for co hi

    #pragma unroll
    for (int ky = 0; ky < 5; ++ky) {
        const uint32_t* abase = &s_in[w + ky][g][2 * tq];  // + (mt*16+kx+?)*8 u32
        #pragma unroll
        for (int kx = 0; kx < 5; ++kx) {
            const int tap = ky * 5 + kx;
            // B fragments (weights): both co halves
            uint2 bLo = *(const uint2*)(wbase + tap * 128);       // co g
            uint2 bHi = *(const uint2*)(wbase + tap * 128 + 64);  // co g+8
            #pragma unroll
            for (int mt = 0; mt < 4; ++mt) {
                // A fragment (input px mt*16+g, mt*16+g+8 at col +kx)
                uint2 aLo = *(const uint2*)(abase + (mt * 16 + kx) * 8);
                uint2 aHi = *(const uint2*)(abase + (mt * 16 + kx + 8) * 8);
                mma_tf32(d[mt][0], aLo.x, aHi.x, aLo.y, aHi.y, bLo.x, bLo.y);
                mma_tf32(d[mt][1], aLo.x, aHi.x, aLo.y, aHi.y, bHi.x, bHi.y);
            }
        }
    }

    // ---- epilogue: D(m=px, n=co): thread has (px g, co 2tq/2tq+1) pairs -> STG.64
    const int gy = y0 + w;
    if (gy < HOUT) {
        float2 bL = make_float2(s_bias[2 * tq],     s_bias[2 * tq + 1]);
        float2 bH = make_float2(s_bias[8 + 2 * tq], s_bias[8 + 2 * tq + 1]);
        float* orow = out + ((long long)(b * HOUT + gy) * WOUT) * COUT;
        #pragma unroll
        for (int mt = 0; mt < 4; ++mt) {
            #pragma unroll
            for (int half = 0; half < 2; ++half) {   // px g / px g+8
                int px = x0 + mt * 16 + g + half * 8;
                if (px < WOUT) {
                    float* p = orow + (long long)px * COUT;
                    float2 lo = make_float2(d[mt][0][2 * half]     + bL.x,
                                            d[mt][0][2 * half + 1] + bL.y);
                    float2 hi = make_float2(d[mt][1][2 * half]     + bH.x,
                                            d[mt][1][2 * half + 1] + bH.y);
                    *(float2*)(p + 2 * tq)     = lo;
                    *(float2*)(p + 8 + 2 * tq) = hi;
                }
            }
        }
    }
}

extern "C" void kernel_launch(void* const* d_in, const int* in_sizes, int n_in,
                              void* d_out, int out_size) {
    const float* inputs = (const float*)d_in[0];
    const float* w3     = (const float*)d_in[1];
    const float* w4     = (const float*)d_in[2];
    const float* w44    = (const float*)d_in[3];
    const float* w6     = (const float*)d_in[4];
    const float* bias   = (const float*)d_in[5];

    build_weights<<<(FS * FS * CIN * COUT + 255) / 256, 256>>>(w3, w4, w44, w6);

    dim3 grid((WOUT + TW - 1) / TW,   // 8
              (HOUT + RT - 1) / RT,   // 64
              BATCHN);                 // 32
    conv_mma_kernel<<<grid, 256>>>(inputs, bias, (float*)d_out);
}

// round 8
// speedup vs baseline: 1.2107x; 1.2107x over previous
#include <cuda_runtime.h>
#include <cstdint>

#define CIN   6
#define COUT  16
#define FS    5
#define HIN   512
#define WIN   512
#define HOUT  508
#define WOUT  508
#define BATCHN 32

// ---- dense weights (fp32), built per launch ----
__device__ float g_Wd[FS * FS * CIN * COUT];

__global__ void build_weights(const float* __restrict__ w3,
                              const float* __restrict__ w4,
                              const float* __restrict__ w44,
                              const float* __restrict__ w6) {
    int idx = blockIdx.x * blockDim.x + threadIdx.x;
    if (idx >= FS * FS * CIN * COUT) return;
    int co = idx % COUT;
    int ci = (idx / COUT) % CIN;
    int kk = idx / (COUT * CIN);
    float v = 0.f;
    if (co < 6) {
        int i = co;
        #pragma unroll
        for (int m = 0; m < 3; ++m)
            if (ci == (i + m) % 6) v = w3[(kk * 3 + m) * 6 + i];
    } else if (co < 12) {
        int k = co - 6;
        #pragma unroll
        for (int m = 0; m < 4; ++m)
            if (ci == (k + m) % 6) v = w4[(kk * 4 + m) * 6 + k];
    } else if (co < 15) {
        int k = co - 12;
        const int off[4] = {0, 1, 3, 4};
        #pragma unroll
        for (int m = 0; m < 4; ++m)
            if (ci == (k + off[m]) % 6) v = w44[(kk * 4 + m) * 3 + k];
    } else {
        v = w6[kk * 6 + ci];
    }
    g_Wd[idx] = v;
}

// ============== mma.sync tf32 conv (R6 structure, 4 CTAs/SM) ==============
// Per mma: D[16 co][8 px]. A = weights (m16 co x k8), B = input (k8 x n8 px).
// K slots = ci permuted [0,4,1,5,2,6,3,7]; slots 5,7 zero. Warp = 1 output
// row x 64 px (8 n-chunks), D accumulates across 25 taps.

#define TW    64
#define RT    8
#define AROWS (RT + 4)    // 12
#define ACOLS (TW + 4)    // 68

__device__ __forceinline__ uint32_t cvt_tf32(float f) {
    uint32_t u;
    asm("cvt.rna.tf32.f32 %0, %1;" : "=r"(u) : "f"(f));
    return u;
}

__device__ __forceinline__ void mma_tf32(float d[4],
                                         uint32_t a0, uint32_t a1,
                                         uint32_t a2, uint32_t a3,
                                         uint32_t b0, uint32_t b1) {
    asm volatile(
        "mma.sync.aligned.m16n8k8.row.col.f32.tf32.tf32.f32 "
        "{%0,%1,%2,%3}, {%4,%5,%6,%7}, {%8,%9}, {%0,%1,%2,%3};"
        : "+f"(d[0]), "+f"(d[1]), "+f"(d[2]), "+f"(d[3])
        : "r"(a0), "r"(a1), "r"(a2), "r"(a3), "r"(b0), "r"(b1));
}

__global__ __launch_bounds__(256, 4) void conv_mma_kernel(
    const float* __restrict__ in,
    const float* __restrict__ bias,
    float* __restrict__ out) {

    __shared__ uint32_t s_in[AROWS][ACOLS][8];   // 26112 B, tf32 bits
    __shared__ uint32_t s_w[25][COUT][8];        // 12800 B, tf32 bits
    __shared__ float s_bias[COUT];

    const int tid = threadIdx.x;
    const int b  = blockIdx.z;
    const int y0 = blockIdx.y * RT;
    const int x0 = blockIdx.x * TW;

    // ---- stage weights: permuted K slots, zero pad slots 5,7 ----
    for (int i = tid; i < 25 * COUT; i += 256) {
        int tap = i / COUT, co = i % COUT;
        s_w[tap][co][5] = 0;
        s_w[tap][co][7] = 0;
    }
    for (int i = tid; i < 25 * COUT * CIN; i += 256) {
        int tap = i / (COUT * CIN);
        int r   = i % (COUT * CIN);
        int co  = r / CIN;
        int ci  = r % CIN;
        int slot = 2 * (ci & 3) + (ci >> 2);
        s_w[tap][co][slot] = cvt_tf32(g_Wd[(tap * CIN + ci) * COUT + co]);
    }
    if (tid < COUT) s_bias[tid] = bias[tid];

    // ---- stage input tile: [row][col][slot], zero pad + boundary zeros ----
    for (int i = tid; i < AROWS * ACOLS; i += 256) {
        int r = i / ACOLS, c = i % ACOLS;
        s_in[r][c][5] = 0;
        s_in[r][c][7] = 0;
    }
    const float* inb = in + (long long)b * (HIN * WIN * CIN);
    for (int i = tid; i < AROWS * ACOLS * CIN; i += 256) {
        int r   = i / (ACOLS * CIN);
        int rem = i - r * (ACOLS * CIN);
        int c   = rem / CIN;
        int ci  = rem - c * CIN;
        int gy = y0 + r, gx = x0 + c;
        float v = 0.f;
        if (gy < HIN && gx < WIN)
            v = inb[(gy * WIN + gx) * CIN + ci];
        int slot = 2 * (ci & 3) + (ci >> 2);
        s_in[r][c][slot] = cvt_tf32(v);
    }
    __syncthreads();

    // ---- per-warp MMA mainloop ----
    const int w    = tid >> 5;    // warp = output row within tile
    const int lane = tid & 31;
    const int g    = lane >> 2;   // group id: A rows (co g, g+8); B col (px g)
    const int tq   = lane & 3;    // thread-in-group: K positions tq, tq+4

    float d[8][4];
    #pragma unroll
    for (int n = 0; n < 8; ++n)
        #pragma unroll
        for (int q = 0; q < 4; ++q) d[n][q] = 0.f;

    #pragma unroll
    for (int ky = 0; ky < 5; ++ky) {
        const int row = w + ky;
        #pragma unroll
        for (int kx = 0; kx < 5; ++kx) {
            const int tap = ky * 5 + kx;
            // A fragment (weights): a0=(g,tq) a1=(g+8,tq) a2=(g,tq+4) a3=(g+8,tq+4)
            uint2 awLo = *(const uint2*)&s_w[tap][g][2 * tq];
            uint2 awHi = *(const uint2*)&s_w[tap][g + 8][2 * tq];
            #pragma unroll
            for (int n = 0; n < 8; ++n) {
                // B fragment (input): b0=(tq, px g), b1=(tq+4, px g)
                uint2 bv = *(const uint2*)&s_in[row][n * 8 + kx + g][2 * tq];
                mma_tf32(d[n], awLo.x, awHi.x, awLo.y, awHi.y, bv.x, bv.y);
            }
        }
    }

    // ---- epilogue: D(m=co, n=px) -> out[...][px][co], add bias ----
    const int gy = y0 + w;
    if (gy < HOUT) {
        const float bLo = s_bias[g];
        const float bHi = s_bias[g + 8];
        float* orow = out + ((long long)(b * HOUT + gy) * WOUT) * COUT;
        #pragma unroll
        for (int n = 0; n < 8; ++n) {
            int px = x0 + n * 8 + 2 * tq;
            if (px < WOUT) {
                float* p = orow + (long long)px * COUT;
                p[g]     = d[n][0] + bLo;
                p[g + 8] = d[n][2] + bHi;
            }
            if (px + 1 < WOUT) {
                float* p = orow + (long long)(px + 1) * COUT;
                p[g]     = d[n][1] + bLo;
                p[g + 8] = d[n][3] + bHi;
            }
        }
    }
}

extern "C" void kernel_launch(void* const* d_in, const int* in_sizes, int n_in,
                              void* d_out, int out_size) {
    const float* inputs = (const float*)d_in[0];
    const float* w3     = (const float*)d_in[1];
    const float* w4     = (const float*)d_in[2];
    const float* w44    = (const float*)d_in[3];
    const float* w6     = (const float*)d_in[4];
    const float* bias   = (const float*)d_in[5];

    build_weights<<<(FS * FS * CIN * COUT + 255) / 256, 256>>>(w3, w4, w44, w6);

    dim3 grid((WOUT + TW - 1) / TW,   // 8
              (HOUT + RT - 1) / RT,   // 64
              BATCHN);                 // 32
    conv_mma_kernel<<<grid, 256>>>(inputs, bias, (float*)d_out);
}

// round 9
// speedup vs baseline: 1.2832x; 1.0599x over previous
#include <cuda_runtime.h>
#include <cstdint>

#define CIN   6
#define COUT  16
#define FS    5
#define HIN   512
#define WIN   512
#define HOUT  508
#define WOUT  508
#define BATCHN 32

// ---- dense weights (fp32), built per launch ----
__device__ float g_Wd[FS * FS * CIN * COUT];

__global__ void build_weights(const float* __restrict__ w3,
                              const float* __restrict__ w4,
                              const float* __restrict__ w44,
                              const float* __restrict__ w6) {
    int idx = blockIdx.x * blockDim.x + threadIdx.x;
    if (idx >= FS * FS * CIN * COUT) return;
    int co = idx % COUT;
    int ci = (idx / COUT) % CIN;
    int kk = idx / (COUT * CIN);
    float v = 0.f;
    if (co < 6) {
        int i = co;
        #pragma unroll
        for (int m = 0; m < 3; ++m)
            if (ci == (i + m) % 6) v = w3[(kk * 3 + m) * 6 + i];
    } else if (co < 12) {
        int k = co - 6;
        #pragma unroll
        for (int m = 0; m < 4; ++m)
            if (ci == (k + m) % 6) v = w4[(kk * 4 + m) * 6 + k];
    } else if (co < 15) {
        int k = co - 12;
        const int off[4] = {0, 1, 3, 4};
        #pragma unroll
        for (int m = 0; m < 4; ++m)
            if (ci == (k + off[m]) % 6) v = w44[(kk * 4 + m) * 3 + k];
    } else {
        v = w6[kk * 6 + ci];
    }
    g_Wd[idx] = v;
}

// ========== mma.sync tf32 conv, 2 output rows per warp (B-reuse) ==========
// Per mma: D[16 co][8 px]. A = weights (m16 x k8), B = input (k8 x n8 px).
// K slots = ci permuted [0,4,1,5,2,6,3,7]; slots 5,7 zero.
// Warp w owns output rows 2w, 2w+1. Iterate source rows sr=0..5: each B
// fragment feeds 2 MMAs (row0 tap ky=sr, row1 tap ky=sr-1). A fragments
// double-buffered in registers (each tap row loaded once).

#define TW    64
#define RT    16            // 8 warps x 2 rows
#define AROWS (RT + 4)      // 20
#define ACOLS (TW + 4)      // 68

#define SIN_BYTES  (AROWS * ACOLS * 8 * 4)   // 43520
#define SW_BYTES   (25 * COUT * 8 * 4)       // 12800
#define SMEM_BYTES (SIN_BYTES + SW_BYTES + COUT * 4)

__device__ __forceinline__ uint32_t cvt_tf32(float f) {
    uint32_t u;
    asm("cvt.rna.tf32.f32 %0, %1;" : "=r"(u) : "f"(f));
    return u;
}

__device__ __forceinline__ void mma_tf32(float d[4],
                                         uint32_t a0, uint32_t a1,
                                         uint32_t a2, uint32_t a3,
                                         uint32_t b0, uint32_t b1) {
    asm volatile(
        "mma.sync.aligned.m16n8k8.row.col.f32.tf32.tf32.f32 "
        "{%0,%1,%2,%3}, {%4,%5,%6,%7}, {%8,%9}, {%0,%1,%2,%3};"
        : "+f"(d[0]), "+f"(d[1]), "+f"(d[2]), "+f"(d[3])
        : "r"(a0), "r"(a1), "r"(a2), "r"(a3), "r"(b0), "r"(b1));
}

__global__ __launch_bounds__(256, 2) void conv_mma_kernel(
    const float* __restrict__ in,
    const float* __restrict__ bias,
    float* __restrict__ out) {

    extern __shared__ char smem[];
    uint32_t (*s_in)[ACOLS][8] = (uint32_t(*)[ACOLS][8])smem;
    uint32_t (*s_w)[COUT][8]   = (uint32_t(*)[COUT][8])(smem + SIN_BYTES);
    float* s_bias = (float*)(smem + SIN_BYTES + SW_BYTES);

    const int tid = threadIdx.x;
    const int b  = blockIdx.z;
    const int y0 = blockIdx.y * RT;
    const int x0 = blockIdx.x * TW;

    // ---- stage weights: permuted K slots, zero pad slots 5,7 ----
    for (int i = tid; i < 25 * COUT; i += 256) {
        int tap = i / COUT, co = i % COUT;
        s_w[tap][co][5] = 0;
        s_w[tap][co][7] = 0;
    }
    for (int i = tid; i < 25 * COUT * CIN; i += 256) {
        int tap = i / (COUT * CIN);
        int r   = i % (COUT * CIN);
        int co  = r / CIN;
        int ci  = r % CIN;
        int slot = 2 * (ci & 3) + (ci >> 2);
        s_w[tap][co][slot] = cvt_tf32(g_Wd[(tap * CIN + ci) * COUT + co]);
    }
    if (tid < COUT) s_bias[tid] = bias[tid];

    // ---- stage input tile: [row][col][slot], zero-pad slots + boundaries ----
    for (int i = tid; i < AROWS * ACOLS; i += 256) {
        int r = i / ACOLS, c = i % ACOLS;
        s_in[r][c][5] = 0;
        s_in[r][c][7] = 0;
    }
    const float* inb = in + (long long)b * (HIN * WIN * CIN);
    for (int i = tid; i < AROWS * ACOLS * CIN; i += 256) {
        int r   = i / (ACOLS * CIN);
        int rem = i - r * (ACOLS * CIN);
        int c   = rem / CIN;
        int ci  = rem - c * CIN;
        int gy = y0 + r, gx = x0 + c;
        float v = 0.f;
        if (gy < HIN && gx < WIN)
            v = inb[(gy * WIN + gx) * CIN + ci];
        int slot = 2 * (ci & 3) + (ci >> 2);
        s_in[r][c][slot] = cvt_tf32(v);
    }
    __syncthreads();

    // ---- per-warp MMA mainloop: 2 output rows ----
    const int w    = tid >> 5;
    const int lane = tid & 31;
    const int g    = lane >> 2;
    const int tq   = lane & 3;
    const int r0   = 2 * w;     // first output row in tile

    float d[2][8][4];
    #pragma unroll
    for (int rr = 0; rr < 2; ++rr)
        #pragma unroll
        for (int n = 0; n < 8; ++n)
            #pragma unroll
            for (int q = 0; q < 4; ++q) d[rr][n][q] = 0.f;

    // A double buffer: aBuf[par][kx][half]
    uint2 aBuf[2][5][2];

    #pragma unroll
    for (int sr = 0; sr < 6; ++sr) {
        const int cur = sr & 1;
        const int prv = cur ^ 1;
        if (sr <= 4) {
            #pragma unroll
            for (int kx = 0; kx < 5; ++kx) {
                const int tap = sr * 5 + kx;
                aBuf[cur][kx][0] = *(const uint2*)&s_w[tap][g][2 * tq];
                aBuf[cur][kx][1] = *(const uint2*)&s_w[tap][g + 8][2 * tq];
            }
        }
        const int row = r0 + sr;
        #pragma unroll
        for (int n = 0; n < 8; ++n) {
            #pragma unroll
            for (int kx = 0; kx < 5; ++kx) {
                uint2 bv = *(const uint2*)&s_in[row][n * 8 + kx + g][2 * tq];
                if (sr <= 4)   // row0, tap ky = sr
                    mma_tf32(d[0][n], aBuf[cur][kx][0].x, aBuf[cur][kx][1].x,
                                      aBuf[cur][kx][0].y, aBuf[cur][kx][1].y,
                                      bv.x, bv.y);
                if (sr >= 1)   // row1, tap ky = sr-1
                    mma_tf32(d[1][n], aBuf[prv][kx][0].x, aBuf[prv][kx][1].x,
                                      aBuf[prv][kx][0].y, aBuf[prv][kx][1].y,
                                      bv.x, bv.y);
            }
        }
    }

    // ---- epilogue: D(m=co, n=px) -> out[...][px][co], add bias ----
    const float bLo = s_bias[g];
    const float bHi = s_bias[g + 8];
    #pragma unroll
    for (int rr = 0; rr < 2; ++rr) {
        const int gy = y0 + r0 + rr;
        if (gy < HOUT) {
            float* orow = out + ((long long)(b * HOUT + gy) * WOUT) * COUT;
            #pragma unroll
            for (int n = 0; n < 8; ++n) {
                int px = x0 + n * 8 + 2 * tq;
                if (px < WOUT) {
                    float* p = orow + (long long)px * COUT;
                    p[g]     = d[rr][n][0] + bLo;
                    p[g + 8] = d[rr][n][2] + bHi;
                }
                if (px + 1 < WOUT) {
                    float* p = orow + (long long)(px + 1) * COUT;
                    p[g]     = d[rr][n][1] + bLo;
                    p[g + 8] = d[rr][n][3] + bHi;
                }
            }
        }
    }
}

extern "C" void kernel_launch(void* const* d_in, const int* in_sizes, int n_in,
                              void* d_out, int out_size) {
    const float* inputs = (const float*)d_in[0];
    const float* w3     = (const float*)d_in[1];
    const float* w4     = (const float*)d_in[2];
    const float* w44    = (const float*)d_in[3];
    const float* w6     = (const float*)d_in[4];
    const float* bias   = (const float*)d_in[5];

    cudaFuncSetAttribute(conv_mma_kernel,
                         cudaFuncAttributeMaxDynamicSharedMemorySize,
                         SMEM_BYTES);

    build_weights<<<(FS * FS * CIN * COUT + 255) / 256, 256>>>(w3, w4, w44, w6);

    dim3 grid((WOUT + TW - 1) / TW,   // 8
              (HOUT + RT - 1) / RT,   // 32
              BATCHN);                 // 32
    conv_mma_kernel<<<grid, 256, SMEM_BYTES>>>(inputs, bias, (float*)d_out);
}

// round 10
// speedup vs baseline: 1.3111x; 1.0217x over previous
#include <cuda_runtime.h>
#include <cstdint>

#define CIN   6
#define COUT  16
#define FS    5
#define HIN   512
#define WIN   512
#define HOUT  508
#define WOUT  508
#define BATCHN 32

// ---- dense weights (fp32), built per launch ----
__device__ float g_Wd[FS * FS * CIN * COUT];

__global__ void build_weights(const float* __restrict__ w3,
                              const float* __restrict__ w4,
                              const float* __restrict__ w44,
                              const float* __restrict__ w6) {
    int idx = blockIdx.x * blockDim.x + threadIdx.x;
    if (idx >= FS * FS * CIN * COUT) return;
    int co = idx % COUT;
    int ci = (idx / COUT) % CIN;
    int kk = idx / (COUT * CIN);
    float v = 0.f;
    if (co < 6) {
        int i = co;
        #pragma unroll
        for (int m = 0; m < 3; ++m)
            if (ci == (i + m) % 6) v = w3[(kk * 3 + m) * 6 + i];
    } else if (co < 12) {
        int k = co - 6;
        #pragma unroll
        for (int m = 0; m < 4; ++m)
            if (ci == (k + m) % 6) v = w4[(kk * 4 + m) * 6 + k];
    } else if (co < 15) {
        int k = co - 12;
        const int off[4] = {0, 1, 3, 4};
        #pragma unroll
        for (int m = 0; m < 4; ++m)
            if (ci == (k + off[m]) % 6) v = w44[(kk * 4 + m) * 3 + k];
    } else {
        v = w6[kk * 6 + ci];
    }
    g_Wd[idx] = v;
}

// ========== mma.sync tf32 conv, 2 rows/warp, kx-outer ILP schedule ==========
// Per mma: D[16 co][8 px]. A = weights (m16 x k8), B = input (k8 x n8 px).
// K slots = ci permuted [0,4,1,5,2,6,3,7]; slots 5,7 zero.
// Warp w owns output rows 2w, 2w+1; source rows sr=0..5; B fragment feeds
// row0 (ky=sr) and row1 (ky=sr-1). A fragments: one LDS.128 per (tap,thread)
// via paired layout; double-buffered across sr.

#define TW    64
#define RT    16            // 8 warps x 2 rows
#define AROWS (RT + 4)      // 20
#define ACOLS (TW + 4)      // 68

#define SIN_BYTES  (AROWS * ACOLS * 8 * 4)   // 43520
#define SW_BYTES   (25 * 8 * 4 * 16)         // 12800 (uint4 per (tap,g,tq))
#define SMEM_BYTES (SIN_BYTES + SW_BYTES + COUT * 4)

__device__ __forceinline__ uint32_t cvt_tf32(float f) {
    uint32_t u;
    asm("cvt.rna.tf32.f32 %0, %1;" : "=r"(u) : "f"(f));
    return u;
}

__device__ __forceinline__ void mma_tf32(float d[4],
                                         uint32_t a0, uint32_t a1,
                                         uint32_t a2, uint32_t a3,
                                         uint32_t b0, uint32_t b1) {
    asm volatile(
        "mma.sync.aligned.m16n8k8.row.col.f32.tf32.tf32.f32 "
        "{%0,%1,%2,%3}, {%4,%5,%6,%7}, {%8,%9}, {%0,%1,%2,%3};"
        : "+f"(d[0]), "+f"(d[1]), "+f"(d[2]), "+f"(d[3])
        : "r"(a0), "r"(a1), "r"(a2), "r"(a3), "r"(b0), "r"(b1));
}

__global__ __launch_bounds__(256, 2) void conv_mma_kernel(
    const float* __restrict__ in,
    const float* __restrict__ bias,
    float* __restrict__ out) {

    extern __shared__ char smem[];
    uint32_t (*s_in)[ACOLS][8] = (uint32_t(*)[ACOLS][8])smem;
    // s_w2[tap][g][tq] = {(g,ktq),(g,ktq+4),(g+8,ktq),(g+8,ktq+4)}
    uint32_t* s_w2 = (uint32_t*)(smem + SIN_BYTES);
    float* s_bias  = (float*)(smem + SIN_BYTES + SW_BYTES);

    const int tid = threadIdx.x;
    const int b  = blockIdx.z;
    const int y0 = blockIdx.y * RT;
    const int x0 = blockIdx.x * TW;

    // ---- stage weights into paired layout ----
    // entry index: ((tap*8 + gg)*4 + tqq)*4 + j ; j0/1 = co gg slots 2tqq/2tqq+1,
    // j2/3 = co gg+8 same slots. slot s holds ci: s=2t -> ci t ; s=2t+1 -> ci t+4.
    for (int i = tid; i < 25 * 8 * 4; i += 256) {   // zero the ci 6,7 slots (tqq 2,3, odd j)
        int tqq = i & 3;
        if (tqq >= 2) {
            s_w2[i * 4 + 1] = 0;
            s_w2[i * 4 + 3] = 0;
        }
    }
    for (int i = tid; i < 25 * COUT * CIN; i += 256) {
        int tap = i / (COUT * CIN);
        int r   = i % (COUT * CIN);
        int co  = r / CIN;
        int ci  = r % CIN;
        int tqq  = ci & 3;
        int kodd = ci >> 2;          // 0: k=tqq, 1: k=tqq+4
        int gg   = co & 7;
        int half = co >> 3;
        uint32_t v = cvt_tf32(g_Wd[(tap * CIN + ci) * COUT + co]);
        s_w2[(((tap * 8 + gg) * 4 + tqq) * 4) + half * 2 + kodd] = v;
    }
    if (tid < COUT) s_bias[tid] = bias[tid];

    // ---- stage input tile: [row][col][slot], zero-pad slots + boundaries ----
    for (int i = tid; i < AROWS * ACOLS; i += 256) {
        int r = i / ACOLS, c = i % ACOLS;
        s_in[r][c][5] = 0;
        s_in[r][c][7] = 0;
    }
    const float* inb = in + (long long)b * (HIN * WIN * CIN);
    for (int i = tid; i < AROWS * ACOLS * CIN; i += 256) {
        int r   = i / (ACOLS * CIN);
        int rem = i - r * (ACOLS * CIN);
        int c   = rem / CIN;
        int ci  = rem - c * CIN;
        int gy = y0 + r, gx = x0 + c;
        float v = 0.f;
        if (gy < HIN && gx < WIN)
            v = inb[(gy * WIN + gx) * CIN + ci];
        int slot = 2 * (ci & 3) + (ci >> 2);
        s_in[r][c][slot] = cvt_tf32(v);
    }
    __syncthreads();

    // ---- per-warp MMA mainloop: 2 output rows, kx-outer for ILP ----
    const int w    = tid >> 5;
    const int lane = tid & 31;
    const int g    = lane >> 2;
    const int tq   = lane & 3;
    const int r0   = 2 * w;

    float d[2][8][4];
    #pragma unroll
    for (int rr = 0; rr < 2; ++rr)
        #pragma unroll
        for (int n = 0; n < 8; ++n)
            #pragma unroll
            for (int q = 0; q < 4; ++q) d[rr][n][q] = 0.f;

    // A double buffer: aBuf[par][kx] = uint4 {a(g,tq),a(g,tq+4),a(g+8,tq),a(g+8,tq+4)}
    uint4 aBuf[2][5];
    const uint32_t* wbase = s_w2 + (g * 4 + tq) * 4;   // + tap*128 u32

    #pragma unroll
    for (int sr = 0; sr < 6; ++sr) {
        const int cur = sr & 1;
        const int prv = cur ^ 1;
        if (sr <= 4) {
            #pragma unroll
            for (int kx = 0; kx < 5; ++kx)
                aBuf[cur][kx] = *(const uint4*)(wbase + (sr * 5 + kx) * 128);
        }
        const uint32_t* brow = &s_in[r0 + sr][g][2 * tq];   // + (n*8+kx)*8 u32
        #pragma unroll
        for (int kx = 0; kx < 5; ++kx) {
            const uint4 aC = aBuf[cur][kx];
            const uint4 aP = aBuf[prv][kx];
            #pragma unroll
            for (int n = 0; n < 8; ++n) {
                uint2 bv = *(const uint2*)(brow + (n * 8 + kx) * 8);
                if (sr <= 4)   // row0, tap ky = sr
                    mma_tf32(d[0][n], aC.x, aC.z, aC.y, aC.w, bv.x, bv.y);
                if (sr >= 1)   // row1, tap ky = sr-1
                    mma_tf32(d[1][n], aP.x, aP.z, aP.y, aP.w, bv.x, bv.y);
            }
        }
    }

    // ---- epilogue: D(m=co, n=px) -> out[...][px][co], add bias ----
    const float bLo = s_bias[g];
    const float bHi = s_bias[g + 8];
    #pragma unroll
    for (int rr = 0; rr < 2; ++rr) {
        const int gy = y0 + r0 + rr;
        if (gy < HOUT) {
            float* orow = out + ((long long)(b * HOUT + gy) * WOUT) * COUT;
            #pragma unroll
            for (int n = 0; n < 8; ++n) {
                int px = x0 + n * 8 + 2 * tq;
                if (px < WOUT) {
                    float* p = orow + (long long)px * COUT;
                    p[g]     = d[rr][n][0] + bLo;
                    p[g + 8] = d[rr][n][2] + bHi;
                }
                if (px + 1 < WOUT) {
                    float* p = orow + (long long)(px + 1) * COUT;
                    p[g]     = d[rr][n][1] + bLo;
                    p[g + 8] = d[rr][n][3] + bHi;
                }
            }
        }
    }
}

extern "C" void kernel_launch(void* const* d_in, const int* in_sizes, int n_in,
                              void* d_out, int out_size) {
    const float* inputs = (const float*)d_in[0];
    const float* w3     = (const float*)d_in[1];
    const float* w4     = (const float*)d_in[2];
    const float* w44    = (const float*)d_in[3];
    const float* w6     = (const float*)d_in[4];
    const float* bias   = (const float*)d_in[5];

    cudaFuncSetAttribute(conv_mma_kernel,
                         cudaFuncAttributeMaxDynamicSharedMemorySize,
                         SMEM_BYTES);

    build_weights<<<(FS * FS * CIN * COUT + 255) / 256, 256>>>(w3, w4, w44, w6);

    dim3 grid((WOUT + TW - 1) / TW,   // 8
              (HOUT + RT - 1) / RT,   // 32
              BATCHN);                 // 32
    conv_mma_kernel<<<grid, 256, SMEM_BYTES>>>(inputs, bias, (float*)d_out);
}

// round 11
// speedup vs baseline: 1.6636x; 1.2688x over previous
#include <cuda_runtime.h>
#include <cstdint>

#define CIN   6
#define COUT  16
#define FS    5
#define HIN   512
#define WIN   512
#define HOUT  508
#define WOUT  508
#define BATCHN 32

// ---- dense weights (fp32), built per launch ----
__device__ float g_Wd[FS * FS * CIN * COUT];

__global__ void build_weights(const float* __restrict__ w3,
                              const float* __restrict__ w4,
                              const float* __restrict__ w44,
                              const float* __restrict__ w6) {
    int idx = blockIdx.x * blockDim.x + threadIdx.x;
    if (idx >= FS * FS * CIN * COUT) return;
    int co = idx % COUT;
    int ci = (idx / COUT) % CIN;
    int kk = idx / (COUT * CIN);
    float v = 0.f;
    if (co < 6) {
        int i = co;
        #pragma unroll
        for (int m = 0; m < 3; ++m)
            if (ci == (i + m) % 6) v = w3[(kk * 3 + m) * 6 + i];
    } else if (co < 12) {
        int k = co - 6;
        #pragma unroll
        for (int m = 0; m < 4; ++m)
            if (ci == (k + m) % 6) v = w4[(kk * 4 + m) * 6 + k];
    } else if (co < 15) {
        int k = co - 12;
        const int off[4] = {0, 1, 3, 4};
        #pragma unroll
        for (int m = 0; m < 4; ++m)
            if (ci == (k + off[m]) % 6) v = w44[(kk * 4 + m) * 3 + k];
    } else {
        v = w6[kk * 6 + ci];
    }
    g_Wd[idx] = v;
}

// ========== mma.sync tf32 conv, 2 rows/warp, low-overhead staging ==========
// Mainloop identical to R10. Staging is div/mod-free; bias rides the spare
// K6 slot (input K6 = 1.0, weight K6 = bias[co] on tap 12), so D = output.
// Array slot s ↔ K position: 0↔K0 1↔K4 2↔K1 3↔K5 4↔K2 5↔K6 6↔K3 7↔K7.
// ci → slot: 2*(ci&3)+(ci>>2). Free: slot5 (K6, bias), slot7 (K7, zero).

#define TW    64
#define RT    16            // 8 warps x 2 rows
#define AROWS (RT + 4)      // 20
#define ACOLS (TW + 4)      // 68

#define SIN_BYTES  (AROWS * ACOLS * 8 * 4)   // 43520
#define SW_BYTES   (25 * 8 * 4 * 16)         // 12800
#define SMEM_BYTES (SIN_BYTES + SW_BYTES)

#define ONE_TF32 0x3F800000u

__device__ __forceinline__ uint32_t cvt_tf32(float f) {
    uint32_t u;
    asm("cvt.rna.tf32.f32 %0, %1;" : "=r"(u) : "f"(f));
    return u;
}

__device__ __forceinline__ void mma_tf32(float d[4],
                                         uint32_t a0, uint32_t a1,
                                         uint32_t a2, uint32_t a3,
                                         uint32_t b0, uint32_t b1) {
    asm volatile(
        "mma.sync.aligned.m16n8k8.row.col.f32.tf32.tf32.f32 "
        "{%0,%1,%2,%3}, {%4,%5,%6,%7}, {%8,%9}, {%0,%1,%2,%3};"
        : "+f"(d[0]), "+f"(d[1]), "+f"(d[2]), "+f"(d[3])
        : "r"(a0), "r"(a1), "r"(a2), "r"(a3), "r"(b0), "r"(b1));
}

__global__ __launch_bounds__(256, 2) void conv_mma_kernel(
    const float* __restrict__ in,
    const float* __restrict__ bias,
    float* __restrict__ out) {

    extern __shared__ char smem[];
    uint32_t (*s_in)[ACOLS][8] = (uint32_t(*)[ACOLS][8])smem;
    uint32_t* s_inf = (uint32_t*)smem;                 // flat view
    // s_w2[tap][gg][tqq][4]: j0/1 = co gg, K tqq / tqq+4 ; j2/3 = co gg+8 same
    uint32_t* s_w2 = (uint32_t*)(smem + SIN_BYTES);

    const int tid = threadIdx.x;
    const int b  = blockIdx.z;
    const int y0 = blockIdx.y * RT;
    const int x0 = blockIdx.x * TW;

    // ---- fill K6 (=1.0 input / bias weight) and K7 (=0) slots ----
    // input: slots 5,7 of every pixel (linear, no div)
    for (int i = tid; i < AROWS * ACOLS; i += 256) {
        s_inf[i * 8 + 5] = ONE_TF32;
        s_inf[i * 8 + 7] = 0;
    }
    // weights: entries (tqq>=2, j odd) = K6/K7; bias on tap 12 K6
    for (int p = tid; p < 25 * 8 * 4; p += 256) {
        int tqq = p & 3;
        if (tqq >= 2) {
            uint32_t v1 = 0, v3 = 0;
            if (tqq == 2 && (p >> 5) == 12) {   // tap 12, K6
                int gg = (p >> 2) & 7;
                v1 = cvt_tf32(bias[gg]);
                v3 = cvt_tf32(bias[8 + gg]);
            }
            s_w2[p * 4 + 1] = v1;
            s_w2[p * 4 + 3] = v3;
        }
    }

    // ---- input staging: threads 0..203, fixed (col, ci-pair) ----
    if (tid < 204) {
        const int c    = tid / 3;          // one div, once
        const int part = tid - 3 * c;      // ci pair {2p, 2p+1}
        const int ci0 = 2 * part, ci1 = 2 * part + 1;
        const int slot0 = 2 * (ci0 & 3) + (ci0 >> 2);
        const int slot1 = 2 * (ci1 & 3) + (ci1 >> 2);
        const int gx = x0 + c;
        const bool xok = gx < WIN;
        const float* ip = in + ((long long)b * HIN * WIN + (long long)y0 * WIN + gx) * CIN
                             + 2 * part;
        uint32_t* sp = &s_in[0][c][0];
        #pragma unroll 4
        for (int r = 0; r < AROWS; ++r) {
            float2 v = make_float2(0.f, 0.f);
            if (xok && (y0 + r) < HIN) v = *(const float2*)ip;
            sp[slot0] = cvt_tf32(v.x);
            sp[slot1] = cvt_tf32(v.y);
            ip += WIN * CIN;
            sp += ACOLS * 8;
        }
    }
    // ---- weight staging: threads 204..251, 2 (co,ci) pairs each ----
    else if (tid < 252) {
        int p0 = 2 * (tid - 204);          // pairs p0, p0+1 (co-major: p = co*6+ci)
        int co = p0 / 6;                   // one div, once
        int ci0 = p0 - 6 * co;
        // pair A: (co, ci0) ; pair B: (co, ci0+1) or (co+1, 0)
        int coB = co, ciB = ci0 + 1;
        if (ciB == 6) { coB = co + 1; ciB = 0; }
        const int ggA = co & 7,  hA = co >> 3;
        const int ggB = coB & 7, hB = coB >> 3;
        const int eA = (ggA * 4 + (ci0 & 3)) * 4 + hA * 2 + (ci0 >> 2);
        const int eB = (ggB * 4 + (ciB & 3)) * 4 + hB * 2 + (ciB >> 2);
        const float* wA = g_Wd + ci0 * COUT + co;
        const float* wB = g_Wd + ciB * COUT + coB;
        #pragma unroll 5
        for (int tap = 0; tap < 25; ++tap) {
            s_w2[tap * 128 + eA] = cvt_tf32(wA[tap * (CIN * COUT)]);
            s_w2[tap * 128 + eB] = cvt_tf32(wB[tap * (CIN * COUT)]);
        }
    }
    __syncthreads();

    // ---- per-warp MMA mainloop: 2 output rows, kx-outer (R10) ----
    const int w    = tid >> 5;
    const int lane = tid & 31;
    const int g    = lane >> 2;
    const int tq   = lane & 3;
    const int r0   = 2 * w;

    float d[2][8][4];
    #pragma unroll
    for (int rr = 0; rr < 2; ++rr)
        #pragma unroll
        for (int n = 0; n < 8; ++n)
            #pragma unroll
            for (int q = 0; q < 4; ++q) d[rr][n][q] = 0.f;

    uint4 aBuf[2][5];
    const uint32_t* wbase = s_w2 + (g * 4 + tq) * 4;

    #pragma unroll
    for (int sr = 0; sr < 6; ++sr) {
        const int cur = sr & 1;
        const int prv = cur ^ 1;
        if (sr <= 4) {
            #pragma unroll
            for (int kx = 0; kx < 5; ++kx)
                aBuf[cur][kx] = *(const uint4*)(wbase + (sr * 5 + kx) * 128);
        }
        const uint32_t* brow = &s_in[r0 + sr][g][2 * tq];
        #pragma unroll
        for (int kx = 0; kx < 5; ++kx) {
            const uint4 aC = aBuf[cur][kx];
            const uint4 aP = aBuf[prv][kx];
            #pragma unroll
            for (int n = 0; n < 8; ++n) {
                uint2 bv = *(const uint2*)(brow + (n * 8 + kx) * 8);
                if (sr <= 4)
                    mma_tf32(d[0][n], aC.x, aC.z, aC.y, aC.w, bv.x, bv.y);
                if (sr >= 1)
                    mma_tf32(d[1][n], aP.x, aP.z, aP.y, aP.w, bv.x, bv.y);
            }
        }
    }

    // ---- epilogue: D(m=co, n=px) -> out[...][px][co] (bias already in D) ----
    #pragma unroll
    for (int rr = 0; rr < 2; ++rr) {
        const int gy = y0 + r0 + rr;
        if (gy < HOUT) {
            float* orow = out + ((long long)(b * HOUT + gy) * WOUT) * COUT;
            #pragma unroll
            for (int n = 0; n < 8; ++n) {
                int px = x0 + n * 8 + 2 * tq;
                if (px < WOUT) {
                    float* p = orow + (long long)px * COUT;
                    p[g]     = d[rr][n][0];
                    p[g + 8] = d[rr][n][2];
                }
                if (px + 1 < WOUT) {
                    float* p = orow + (long long)(px + 1) * COUT;
                    p[g]     = d[rr][n][1];
                    p[g + 8] = d[rr][n][3];
                }
            }
        }
    }
}

extern "C" void kernel_launch(void* const* d_in, const int* in_sizes, int n_in,
                              void* d_out, int out_size) {
    const float* inputs = (const float*)d_in[0];
    const float* w3     = (const float*)d_in[1];
    const float* w4     = (const float*)d_in[2];
    const float* w44    = (const float*)d_in[3];
    const float* w6     = (const float*)d_in[4];
    const float* bias   = (const float*)d_in[5];

    cudaFuncSetAttribute(conv_mma_kernel,
                         cudaFuncAttributeMaxDynamicSharedMemorySize,
                         SMEM_BYTES);

    build_weights<<<(FS * FS * CIN * COUT + 255) / 256, 256>>>(w3, w4, w44, w6);

    dim3 grid((WOUT + TW - 1) / TW,   // 8
              (HOUT + RT - 1) / RT,   // 32
              BATCHN);                 // 32
    conv_mma_kernel<<<grid, 256, SMEM_BYTES>>>(inputs, bias, (float*)d_out);
}